// round 9
// baseline (speedup 1.0000x reference)
#include <cuda_runtime.h>
#include <cuda_fp16.h>
#include <math.h>
#include <stdint.h>

#define BD 4096
#define HD 512
#define G4 2048    // 4*H
#define NS 16
#define NB 16      // n-blocks per step GEMM (G4/128)
#define MB 32      // m-blocks (BD/128)

// ======================= device scratch (allocation-free) =======================
__device__ __half g_Whh_hi[G4*HD], g_Whh_lo[G4*HD];     // permuted n'=4j+g, K-major
__device__ __half g_Wih_hi[G4*HD], g_Wih_lo[G4*HD];
__device__ __half g_Wout_hi[HD*HD], g_Wout_lo[HD*HD];
__device__ __half g_x_hi[(size_t)BD*HD], g_x_lo[(size_t)BD*HD];
__device__ __half g_h_hi[2][(size_t)BD*HD], g_h_lo[2][(size_t)BD*HD];
__device__ __half g_hf_hi[(size_t)BD*HD], g_hf_lo[(size_t)BD*HD];
__device__ float g_wflag[G4], g_bias[G4];
__device__ float g_xb[(size_t)BD*G4];
__device__ float g_hs[(size_t)NS*BD*HD];
__device__ float g_cs[(size_t)NS*BD*HD];
__device__ float g_pbuf[NS*BD];
// ---- ACT early-halt state ----
__device__ float g_halt[NS*BD];     // halt prob per (step,row)
__device__ float g_cum[BD];         // running cumsum of halt
__device__ int   g_max_needed;      // last step index that must execute
__device__ int   g_cnt[NS];         // halted-row counts per step
__device__ int   g_arrive[NS];      // mblock-level arrival counters
__device__ int   g_mb_arrive[NS*MB];// CTA arrival counters per (step, mblock)
__device__ float g_part[NB*BD];     // per-nblock halt-dot partials

// ======================= helpers =======================
__device__ __forceinline__ float sigf(float x) {
    return __fdividef(1.f, 1.f + __expf(-x));
}
__device__ __forceinline__ float tanh_acc(float x) {
    float ax = fabsf(x);
    float e  = __expf(-2.f * ax);
    float t  = __fdividef(1.f - e, 1.f + e);
    return copysignf(t, x);
}
__device__ __forceinline__ uint32_t smem_u32(const void* p) {
    uint32_t a;
    asm("{ .reg .u64 t; cvta.to.shared.u64 t, %1; cvt.u32.u64 %0, t; }" : "=r"(a) : "l"(p));
    return a;
}
__device__ __forceinline__ void cpa16(uint32_t d, const void* s) {
    asm volatile("cp.async.cg.shared.global [%0], [%1], 16;" :: "r"(d), "l"(s));
}
__device__ __forceinline__ void cpa_commit() { asm volatile("cp.async.commit_group;"); }
template <int N> __device__ __forceinline__ void cpa_wait() {
    asm volatile("cp.async.wait_group %0;" :: "n"(N));
}
__device__ __forceinline__ void ldsm4(uint32_t* r, uint32_t a) {
    asm volatile("ldmatrix.sync.aligned.m8n8.x4.shared.b16 {%0,%1,%2,%3}, [%4];"
        : "=r"(r[0]), "=r"(r[1]), "=r"(r[2]), "=r"(r[3]) : "r"(a));
}
__device__ __forceinline__ void mma16816(float* c, const uint32_t* a, const uint32_t* b) {
    asm volatile("mma.sync.aligned.m16n8k16.row.col.f32.f16.f16.f32 "
        "{%0,%1,%2,%3}, {%4,%5,%6,%7}, {%8,%9}, {%0,%1,%2,%3};"
        : "+f"(c[0]), "+f"(c[1]), "+f"(c[2]), "+f"(c[3])
        : "r"(a[0]), "r"(a[1]), "r"(a[2]), "r"(a[3]), "r"(b[0]), "r"(b[1]));
}

// smem tile layout: 128 rows x 64B (4 x 16B chunks), XOR-swizzled:
//   phys_chunk = c ^ ((row>>1)&3)  -> conflict-free ldmatrix row sets
#define TILE_BYTES 8192
#define STAGE_BYTES 32768           // Ahi | Alo | Bhi | Blo
#define NSTAGE 3
#define DSMEM_BYTES (NSTAGE * STAGE_BYTES)   // 96KB; C-tile (67.6KB) reuses it
#define CSTRIDE 132

// ======================= prep kernels =======================
__global__ void prep_weights(const float* __restrict__ Wih, const float* __restrict__ Whh,
                             const float* __restrict__ bih, const float* __restrict__ bhh) {
    int idx = blockIdx.x * blockDim.x + threadIdx.x;
    if (idx >= G4 * HD) return;
    int np = idx >> 9, k = idx & 511;
    int j = np >> 2, g = np & 3;
    int row = g * HD + j;
    float wh = Whh[row * HD + k];
    __half h1 = __float2half(wh);
    g_Whh_hi[idx] = h1;
    g_Whh_lo[idx] = __float2half(wh - __half2float(h1));
    float wi = Wih[row * (HD + 1) + 1 + k];
    __half i1 = __float2half(wi);
    g_Wih_hi[idx] = i1;
    g_Wih_lo[idx] = __float2half(wi - __half2float(i1));
    if (k == 0) {
        g_wflag[np] = Wih[row * (HD + 1)];
        g_bias [np] = bih[row] + bhh[row];
    }
}

__global__ void prep_data(const float* __restrict__ x, const float* __restrict__ h0,
                          const float* __restrict__ Wout) {
    size_t idx = (size_t)blockIdx.x * blockDim.x + threadIdx.x;
    if (idx < (size_t)BD * HD) {
        float v = x[idx];
        __half hv = __float2half(v);
        g_x_hi[idx] = hv;
        g_x_lo[idx] = __float2half(v - __half2float(hv));
        float h = h0[idx];
        __half hh = __float2half(h);
        g_h_hi[0][idx] = hh;
        g_h_lo[0][idx] = __float2half(h - __half2float(hh));
    }
    if (idx < (size_t)HD * HD) {
        float w = Wout[idx];
        __half wh = __float2half(w);
        g_Wout_hi[idx] = wh;
        g_Wout_lo[idx] = __float2half(w - __half2float(wh));
    }
    // ---- per-launch ACT state reset ----
    if (idx < BD) g_cum[idx] = 0.f;
    if (idx < NS) { g_cnt[idx] = 0; g_arrive[idx] = 0; }
    if (idx < NS * MB) g_mb_arrive[idx] = 0;
    if (idx == 0) g_max_needed = NS - 1;
}

// ======================= mma.sync GEMM + fused epilogue =======================
// C[M, Ntot] = (Ahi+Alo)[M,512] * (Bhi+Blo)[Ntot,512]^T   (fp16x3, fp32 acc)
// MODE 0: Cout = acc + bias
// MODE 1: LSTM gate epilogue + fused halt reduction; skips when sidx > g_max_needed
template <int MODE>
__global__ void __launch_bounds__(256, 2)
mma_gemm(const __half* __restrict__ Ahi, const __half* __restrict__ Alo,
         const __half* __restrict__ Bhi, const __half* __restrict__ Blo,
         int Ntot, const float* __restrict__ bias, float* __restrict__ Cout,
         const float* __restrict__ xb, const float* __restrict__ wflag, int sidx,
         const float* __restrict__ c_in, float* __restrict__ h_out, float* __restrict__ c_out,
         __half* __restrict__ hhi_out, __half* __restrict__ hlo_out,
         const float* __restrict__ Whalt, const float* __restrict__ bhalt)
{
    if (MODE == 1 && sidx > g_max_needed) return;   // all rows halted -> dead step

    extern __shared__ char dsm[];
    const int tid  = threadIdx.x;
    const int wid  = tid >> 5;
    const int lane = tid & 31;
    const int m0 = blockIdx.y * 128;
    const int n0 = blockIdx.x * 128;
    const int wm = (wid & 3) * 32;    // warp m offset within tile
    const int wn = (wid >> 2) * 64;   // warp n offset within tile

    const uint32_t sbase = smem_u32(dsm);

    float acc[2][8][4];
#pragma unroll
    for (int a = 0; a < 2; a++)
#pragma unroll
        for (int b = 0; b < 8; b++)
#pragma unroll
            for (int q = 0; q < 4; q++) acc[a][b][q] = 0.f;

    // ---- stage loader: Ahi/Alo 128x32, Bhi/Blo 128x32 fp16, swizzled ----
    auto load_stage = [&](int kc, int s) {
        uint32_t st = sbase + s * STAGE_BYTES;
#pragma unroll
        for (int i = 0; i < 2; i++) {
            int cid = tid + i * 256;            // 0..511
            int row = cid >> 2, c = cid & 3;
            uint32_t off = row * 64 + ((c ^ ((row >> 1) & 3)) << 4);
            size_t ga = (size_t)(m0 + row) * 512 + kc * 32 + c * 8;
            size_t gb = (size_t)(n0 + row) * 512 + kc * 32 + c * 8;
            cpa16(st + off,                  Ahi + ga);
            cpa16(st + TILE_BYTES + off,     Alo + ga);
            cpa16(st + 2 * TILE_BYTES + off, Bhi + gb);
            cpa16(st + 3 * TILE_BYTES + off, Blo + gb);
        }
        cpa_commit();
    };

    // ---- per-chunk compute: stream B fragments one n-group (n16) at a time ----
    auto compute = [&](int s) {
        uint32_t st = sbase + s * STAGE_BYTES;
#pragma unroll
        for (int k16 = 0; k16 < 2; k16++) {
            uint32_t ahi[2][4], alo[2][4];
#pragma unroll
            for (int mt = 0; mt < 2; mt++) {
                int row = wm + mt * 16 + (lane & 7) + ((lane >> 3) & 1) * 8;
                int ch  = k16 * 2 + (lane >> 4);
                uint32_t off = row * 64 + ((ch ^ ((row >> 1) & 3)) << 4);
                ldsm4(ahi[mt], st + off);
                ldsm4(alo[mt], st + TILE_BYTES + off);
            }
#pragma unroll
            for (int ng = 0; ng < 4; ng++) {
                uint32_t bh[4], bl[4];
                int row = wn + ng * 16 + (lane & 7) + ((lane >> 4) & 1) * 8;
                int ch  = k16 * 2 + ((lane >> 3) & 1);
                uint32_t off = row * 64 + ((ch ^ ((row >> 1) & 3)) << 4);
                ldsm4(bh, st + 2 * TILE_BYTES + off);
                ldsm4(bl, st + 3 * TILE_BYTES + off);
#pragma unroll
                for (int mt = 0; mt < 2; mt++)
#pragma unroll
                    for (int nf = 0; nf < 2; nf++)
                        mma16816(acc[mt][ng * 2 + nf], ahi[mt], &bh[nf * 2]);
#pragma unroll
                for (int mt = 0; mt < 2; mt++)
#pragma unroll
                    for (int nf = 0; nf < 2; nf++)
                        mma16816(acc[mt][ng * 2 + nf], ahi[mt], &bl[nf * 2]);
#pragma unroll
                for (int mt = 0; mt < 2; mt++)
#pragma unroll
                    for (int nf = 0; nf < 2; nf++)
                        mma16816(acc[mt][ng * 2 + nf], alo[mt], &bh[nf * 2]);
            }
        }
    };

    // ---- 3-stage pipeline over 16 K-chunks ----
    load_stage(0, 0);
    load_stage(1, 1);
    for (int kc = 0; kc < 16; kc++) {
        cpa_wait<1>();
        __syncthreads();
        if (kc + 2 < 16) load_stage(kc + 2, (kc + 2) % NSTAGE);
        compute(kc % NSTAGE);
    }
    __syncthreads();   // all reads of stage smem done -> reuse as C tile

    // ---- spill accumulators to smem C tile [128][CSTRIDE] ----
    float* Cs = (float*)dsm;
#pragma unroll
    for (int mt = 0; mt < 2; mt++)
#pragma unroll
        for (int nf = 0; nf < 8; nf++) {
            int row = wm + mt * 16 + (lane >> 2);
            int col = wn + nf * 8 + (lane & 3) * 2;
            Cs[row * CSTRIDE + col]           = acc[mt][nf][0];
            Cs[row * CSTRIDE + col + 1]       = acc[mt][nf][1];
            Cs[(row + 8) * CSTRIDE + col]     = acc[mt][nf][2];
            Cs[(row + 8) * CSTRIDE + col + 1] = acc[mt][nf][3];
        }
    __syncthreads();

    // ---- final epilogue: thread -> (row ml, 64-col half) ----
    const int ml = tid >> 1;
    const int colbase = (tid & 1) * 64;
    const int m = m0 + ml;

    if (MODE == 0) {
#pragma unroll
        for (int q = 0; q < 16; q++) {
            int ncol = colbase + q * 4;
            float4 v  = *(float4*)&Cs[ml * CSTRIDE + ncol];
            float4 bv = *(const float4*)&bias[n0 + ncol];
            v.x += bv.x; v.y += bv.y; v.z += bv.z; v.w += bv.w;
            *(float4*)&Cout[(size_t)m * Ntot + n0 + ncol] = v;
        }
    } else {
        const int j0 = (n0 + colbase) >> 2;   // first hidden unit for this thread
        const int step0 = (sidx == 0);
        float cold[16];
#pragma unroll
        for (int q = 0; q < 16; q += 4) {
            float4 cv = *(const float4*)&c_in[(size_t)m * HD + j0 + q];
            cold[q] = cv.x; cold[q + 1] = cv.y; cold[q + 2] = cv.z; cold[q + 3] = cv.w;
        }
        float hbuf[16], cbuf[16];
#pragma unroll
        for (int q = 0; q < 16; q++) {
            int ncol = colbase + q * 4;
            float4 a  = *(float4*)&Cs[ml * CSTRIDE + ncol];
            float4 xv = *(const float4*)&xb[(size_t)m * G4 + n0 + ncol];
            float gi = a.x + xv.x, gf = a.y + xv.y, gg = a.z + xv.z, go = a.w + xv.w;
            if (step0) {
                float4 wf = *(const float4*)&wflag[n0 + ncol];
                gi += wf.x; gf += wf.y; gg += wf.z; go += wf.w;
            }
            float cn = sigf(gf) * cold[q] + sigf(gi) * tanh_acc(gg);
            float hn = sigf(go) * tanh_acc(cn);
            hbuf[q] = hn; cbuf[q] = cn;
        }
#pragma unroll
        for (int q = 0; q < 16; q += 4) {
            *(float4*)&h_out[(size_t)m * HD + j0 + q] = make_float4(hbuf[q], hbuf[q+1], hbuf[q+2], hbuf[q+3]);
            *(float4*)&c_out[(size_t)m * HD + j0 + q] = make_float4(cbuf[q], cbuf[q+1], cbuf[q+2], cbuf[q+3]);
        }
        __half hh[16], hl[16];
#pragma unroll
        for (int q = 0; q < 16; q++) {
            hh[q] = __float2half(hbuf[q]);
            hl[q] = __float2half(hbuf[q] - __half2float(hh[q]));
        }
        *(uint4*)&hhi_out[(size_t)m * HD + j0]     = *(uint4*)&hh[0];
        *(uint4*)&hhi_out[(size_t)m * HD + j0 + 8] = *(uint4*)&hh[8];
        *(uint4*)&hlo_out[(size_t)m * HD + j0]     = *(uint4*)&hl[0];
        *(uint4*)&hlo_out[(size_t)m * HD + j0 + 8] = *(uint4*)&hl[8];

        // ---- fused halt partial: this thread's 16 hidden units ----
        float hp = 0.f;
#pragma unroll
        for (int q = 0; q < 16; q++) hp += hbuf[q] * Whalt[j0 + q];
        hp += __shfl_xor_sync(0xffffffffu, hp, 1);   // pair covers the nblock's 32 units
        if ((tid & 1) == 0) g_part[(size_t)blockIdx.x * BD + m] = hp;
        __threadfence();
        __syncthreads();

        __shared__ int s_last;
        if (tid == 0) {
            int old = atomicAdd(&g_mb_arrive[sidx * MB + blockIdx.y], 1);
            s_last = (old == NB - 1);
        }
        __syncthreads();
        if (s_last) {
            int halted = 0;
            if (tid < 128) {
                int m2 = m0 + tid;
                float dot = 0.f;
#pragma unroll
                for (int nb = 0; nb < NB; nb++) dot += g_part[(size_t)nb * BD + m2];
                float halt = sigf(dot + bhalt[0]);
                float cum = g_cum[m2] + halt;
                g_cum[m2] = cum;
                g_halt[sidx * BD + m2] = halt;
                halted = (cum >= 1.0f - 0.01f) ? 1 : 0;
            }
            int c = __syncthreads_count(halted);
            if (tid == 0) {
                atomicAdd(&g_cnt[sidx], c);
                __threadfence();
                int a2 = atomicAdd(&g_arrive[sidx], 1);
                if (a2 == MB - 1) {
                    int tot = atomicAdd(&g_cnt[sidx], 0);   // coherent read
                    if (tot == BD) atomicMin(&g_max_needed, sidx);
                }
            }
        }
    }
}

// ======================= final halting scan (reads precomputed halts) ==============
__global__ void halt_final(float* __restrict__ ponder_out)
{
    int m = blockIdx.x * blockDim.x + threadIdx.x;
    if (m >= BD) return;
    const float thresh = 1.0f - 0.01f;
    float halts[NS];
    float cum = 0.f; int nh = NS - 1; bool found = false;
#pragma unroll
    for (int n = 0; n < NS; n++) {
        halts[n] = g_halt[n * BD + m];   // stale beyond g_max_needed: harmless (p=0 there)
        cum += halts[n];
        if (!found && cum >= thresh) { nh = n; found = true; }
    }
    float s = 0.f;
#pragma unroll
    for (int n = 0; n < NS; n++) {
        float p = 0.f;
        if (n < nh) { p = halts[n]; s += p; }
        g_pbuf[n * BD + m] = p;
    }
    float r = 1.f - s;
    g_pbuf[nh * BD + m] = r;
    ponder_out[m] = (float)nh + 1.f + r;
}

// ======================= weighted reduce + fp16 split for out-GEMM =======================
__global__ void pfin(float* __restrict__ hfin, float* __restrict__ cfin)
{
    int m = blockIdx.x;
    int j = threadIdx.x;
    __shared__ float ps[NS];
    if (j < NS) ps[j] = g_pbuf[j * BD + m];
    __syncthreads();
    float ah = 0.f, ac = 0.f;
#pragma unroll
    for (int n = 0; n < NS; n++) {
        float p = ps[n];
        if (p != 0.f) {                 // skip dead steps: no loads, identical sum
            size_t o = ((size_t)n * BD + m) * HD + j;
            ah += p * g_hs[o];
            ac += p * g_cs[o];
        }
    }
    hfin[(size_t)m * HD + j] = ah;
    cfin[(size_t)m * HD + j] = ac;
    __half hh = __float2half(ah);
    g_hf_hi[(size_t)m * HD + j] = hh;
    g_hf_lo[(size_t)m * HD + j] = __float2half(ah - __half2float(hh));
}

// ======================= launcher =======================
extern "C" void kernel_launch(void* const* d_in, const int* in_sizes, int n_in,
                              void* d_out, int out_size)
{
    const float* x     = (const float*)d_in[0];
    const float* h0    = (const float*)d_in[1];
    const float* c0    = (const float*)d_in[2];
    const float* Wih   = (const float*)d_in[3];
    const float* bih   = (const float*)d_in[4];
    const float* Whh   = (const float*)d_in[5];
    const float* bhh   = (const float*)d_in[6];
    const float* Whalt = (const float*)d_in[7];
    const float* bhalt = (const float*)d_in[8];
    const float* Wout  = (const float*)d_in[9];
    const float* bout  = (const float*)d_in[10];
    (void)in_sizes; (void)n_in; (void)out_size;

    float* out   = (float*)d_out;
    float* out_y = out;
    float* out_h = out + (size_t)BD * HD;
    float* out_c = out + (size_t)BD * HD * 2;
    float* out_p = out + (size_t)BD * HD * 3;

    cudaFuncSetAttribute(mma_gemm<0>, cudaFuncAttributeMaxDynamicSharedMemorySize, DSMEM_BYTES);
    cudaFuncSetAttribute(mma_gemm<1>, cudaFuncAttributeMaxDynamicSharedMemorySize, DSMEM_BYTES);

    __half *Whh_hi, *Whh_lo, *Wih_hi, *Wih_lo, *Wout_hi, *Wout_lo;
    __half *x_hi, *x_lo, *h_hi, *h_lo, *hf_hi, *hf_lo;
    float *wflag, *biasp, *xb, *hs, *cs;
    cudaGetSymbolAddress((void**)&Whh_hi, g_Whh_hi);
    cudaGetSymbolAddress((void**)&Whh_lo, g_Whh_lo);
    cudaGetSymbolAddress((void**)&Wih_hi, g_Wih_hi);
    cudaGetSymbolAddress((void**)&Wih_lo, g_Wih_lo);
    cudaGetSymbolAddress((void**)&Wout_hi, g_Wout_hi);
    cudaGetSymbolAddress((void**)&Wout_lo, g_Wout_lo);
    cudaGetSymbolAddress((void**)&x_hi, g_x_hi);
    cudaGetSymbolAddress((void**)&x_lo, g_x_lo);
    cudaGetSymbolAddress((void**)&h_hi, g_h_hi);
    cudaGetSymbolAddress((void**)&h_lo, g_h_lo);
    cudaGetSymbolAddress((void**)&hf_hi, g_hf_hi);
    cudaGetSymbolAddress((void**)&hf_lo, g_hf_lo);
    cudaGetSymbolAddress((void**)&wflag, g_wflag);
    cudaGetSymbolAddress((void**)&biasp, g_bias);
    cudaGetSymbolAddress((void**)&xb, g_xb);
    cudaGetSymbolAddress((void**)&hs, g_hs);
    cudaGetSymbolAddress((void**)&cs, g_cs);

    const size_t HBUF = (size_t)BD * HD;

    // 1) prep (also resets ACT state per launch)
    prep_weights<<<(G4 * HD + 255) / 256, 256>>>(Wih, Whh, bih, bhh);
    prep_data<<<(BD * HD + 255) / 256, 256>>>(x, h0, Wout);

    // 2) x-part: xb = x @ Wih_p^T + (b_ih + b_hh)
    dim3 gridG(G4 / 128, BD / 128);
    mma_gemm<0><<<gridG, 256, DSMEM_BYTES>>>(x_hi, x_lo, Wih_hi, Wih_lo, G4, biasp, xb,
                                             nullptr, nullptr, -1, nullptr, nullptr, nullptr,
                                             nullptr, nullptr, nullptr, nullptr);

    // 3) recurrent steps with fused halt reduction; dead steps self-skip.
    for (int n = 0; n < NS; n++) {
        const float* c_i = (n == 0) ? c0 : (cs + (size_t)(n - 1) * HBUF);
        mma_gemm<1><<<gridG, 256, DSMEM_BYTES>>>(
            h_hi + (size_t)(n & 1) * HBUF, h_lo + (size_t)(n & 1) * HBUF,
            Whh_hi, Whh_lo, G4, nullptr, nullptr,
            xb, wflag, n,
            c_i, hs + (size_t)n * HBUF, cs + (size_t)n * HBUF,
            h_hi + (size_t)((n + 1) & 1) * HBUF, h_lo + (size_t)((n + 1) & 1) * HBUF,
            Whalt, bhalt);
    }

    // 4) halting probabilities + ponder (from precomputed halts)
    halt_final<<<BD / 256, 256>>>(out_p);

    // 5) h_fin / c_fin (+ fp16 split), skipping p==0 steps
    pfin<<<BD, HD>>>(out_h, out_c);

    // 6) output = h_fin @ W_out^T + b_out
    dim3 gridO(HD / 128, BD / 128);
    mma_gemm<0><<<gridO, 256, DSMEM_BYTES>>>(hf_hi, hf_lo, Wout_hi, Wout_lo, HD, bout, out_y,
                                             nullptr, nullptr, -1, nullptr, nullptr, nullptr,
                                             nullptr, nullptr, nullptr, nullptr);
}

// round 10
// speedup vs baseline: 1.0834x; 1.0834x over previous
#include <cuda_runtime.h>
#include <cuda_fp16.h>
#include <math.h>
#include <stdint.h>

#define BD 4096
#define HD 512
#define G4 2048    // 4*H
#define NS 16

// ======================= device scratch (allocation-free) =======================
__device__ __half g_Whh_hi[G4*HD], g_Whh_lo[G4*HD];     // permuted n'=4j+g, K-major
__device__ __half g_Wih_hi[G4*HD], g_Wih_lo[G4*HD];
__device__ __half g_Wout_hi[HD*HD], g_Wout_lo[HD*HD];
__device__ __half g_x_hi[(size_t)BD*HD], g_x_lo[(size_t)BD*HD];
__device__ __half g_h_hi[2][(size_t)BD*HD], g_h_lo[2][(size_t)BD*HD];
__device__ __half g_hf_hi[(size_t)BD*HD], g_hf_lo[(size_t)BD*HD];
__device__ float g_wflag[G4], g_bias[G4];
__device__ float g_xb[(size_t)BD*G4];
__device__ float g_hs[(size_t)NS*BD*HD];
__device__ float g_cs[(size_t)NS*BD*HD];
// ---- ACT early-halt state ----
__device__ float g_halt[NS*BD];     // halt prob per (step,row)
__device__ float g_cum[BD];         // running cumsum of halt
__device__ int   g_max_needed;      // last step index that must execute
__device__ int   g_cnt[NS];         // halted-row counts per step
__device__ int   g_arrive[NS];      // block arrival counters (last-block pattern)

// ======================= helpers =======================
__device__ __forceinline__ float sigf(float x) {
    return __fdividef(1.f, 1.f + __expf(-x));
}
__device__ __forceinline__ float tanh_acc(float x) {
    float ax = fabsf(x);
    float e  = __expf(-2.f * ax);
    float t  = __fdividef(1.f - e, 1.f + e);
    return copysignf(t, x);
}
__device__ __forceinline__ uint32_t smem_u32(const void* p) {
    uint32_t a;
    asm("{ .reg .u64 t; cvta.to.shared.u64 t, %1; cvt.u32.u64 %0, t; }" : "=r"(a) : "l"(p));
    return a;
}
__device__ __forceinline__ void cpa16(uint32_t d, const void* s) {
    asm volatile("cp.async.cg.shared.global [%0], [%1], 16;" :: "r"(d), "l"(s));
}
__device__ __forceinline__ void cpa_commit() { asm volatile("cp.async.commit_group;"); }
template <int N> __device__ __forceinline__ void cpa_wait() {
    asm volatile("cp.async.wait_group %0;" :: "n"(N));
}
__device__ __forceinline__ void ldsm4(uint32_t* r, uint32_t a) {
    asm volatile("ldmatrix.sync.aligned.m8n8.x4.shared.b16 {%0,%1,%2,%3}, [%4];"
        : "=r"(r[0]), "=r"(r[1]), "=r"(r[2]), "=r"(r[3]) : "r"(a));
}
__device__ __forceinline__ void mma16816(float* c, const uint32_t* a, const uint32_t* b) {
    asm volatile("mma.sync.aligned.m16n8k16.row.col.f32.f16.f16.f32 "
        "{%0,%1,%2,%3}, {%4,%5,%6,%7}, {%8,%9}, {%0,%1,%2,%3};"
        : "+f"(c[0]), "+f"(c[1]), "+f"(c[2]), "+f"(c[3])
        : "r"(a[0]), "r"(a[1]), "r"(a[2]), "r"(a[3]), "r"(b[0]), "r"(b[1]));
}

// smem tile layout: 128 rows x 64B (4 x 16B chunks), XOR-swizzled:
//   phys_chunk = c ^ ((row>>1)&3)  -> conflict-free ldmatrix row sets
#define TILE_BYTES 8192
#define STAGE_BYTES 32768           // Ahi | Alo | Bhi | Blo
#define NSTAGE 3
#define DSMEM_BYTES (NSTAGE * STAGE_BYTES)   // 96KB; C-tile (67.6KB) reuses it
#define CSTRIDE 132

// ======================= prep kernels =======================
__global__ void prep_weights(const float* __restrict__ Wih, const float* __restrict__ Whh,
                             const float* __restrict__ bih, const float* __restrict__ bhh) {
    int idx = blockIdx.x * blockDim.x + threadIdx.x;
    if (idx >= G4 * HD) return;
    int np = idx >> 9, k = idx & 511;
    int j = np >> 2, g = np & 3;
    int row = g * HD + j;
    float wh = Whh[row * HD + k];
    __half h1 = __float2half(wh);
    g_Whh_hi[idx] = h1;
    g_Whh_lo[idx] = __float2half(wh - __half2float(h1));
    float wi = Wih[row * (HD + 1) + 1 + k];
    __half i1 = __float2half(wi);
    g_Wih_hi[idx] = i1;
    g_Wih_lo[idx] = __float2half(wi - __half2float(i1));
    if (k == 0) {
        g_wflag[np] = Wih[row * (HD + 1)];
        g_bias [np] = bih[row] + bhh[row];
    }
}

__global__ void prep_data(const float* __restrict__ x, const float* __restrict__ h0,
                          const float* __restrict__ Wout) {
    size_t idx = (size_t)blockIdx.x * blockDim.x + threadIdx.x;
    if (idx < (size_t)BD * HD) {
        float v = x[idx];
        __half hv = __float2half(v);
        g_x_hi[idx] = hv;
        g_x_lo[idx] = __float2half(v - __half2float(hv));
        float h = h0[idx];
        __half hh = __float2half(h);
        g_h_hi[0][idx] = hh;
        g_h_lo[0][idx] = __float2half(h - __half2float(hh));
    }
    if (idx < (size_t)HD * HD) {
        float w = Wout[idx];
        __half wh = __float2half(w);
        g_Wout_hi[idx] = wh;
        g_Wout_lo[idx] = __float2half(w - __half2float(wh));
    }
    // ---- per-launch ACT state reset ----
    if (idx < BD) g_cum[idx] = 0.f;
    if (idx < NS) { g_cnt[idx] = 0; g_arrive[idx] = 0; }
    if (idx == 0) g_max_needed = NS - 1;
}

// ======================= mma.sync GEMM + fused epilogue =======================
// C[M, Ntot] = (Ahi+Alo)[M,512] * (Bhi+Blo)[Ntot,512]^T   (fp16x3, fp32 acc)
// MODE 0: Cout = acc + bias
// MODE 1: LSTM gate epilogue; skips entirely when step sidx > g_max_needed (ACT)
template <int MODE>
__global__ void __launch_bounds__(256, 2)
mma_gemm(const __half* __restrict__ Ahi, const __half* __restrict__ Alo,
         const __half* __restrict__ Bhi, const __half* __restrict__ Blo,
         int Ntot, const float* __restrict__ bias, float* __restrict__ Cout,
         const float* __restrict__ xb, const float* __restrict__ wflag, int sidx,
         const float* __restrict__ c_in, float* __restrict__ h_out, float* __restrict__ c_out,
         __half* __restrict__ hhi_out, __half* __restrict__ hlo_out)
{
    if (MODE == 1 && sidx > g_max_needed) return;   // all rows halted -> dead step

    extern __shared__ char dsm[];
    const int tid  = threadIdx.x;
    const int wid  = tid >> 5;
    const int lane = tid & 31;
    const int m0 = blockIdx.y * 128;
    const int n0 = blockIdx.x * 128;
    const int wm = (wid & 3) * 32;    // warp m offset within tile
    const int wn = (wid >> 2) * 64;   // warp n offset within tile

    const uint32_t sbase = smem_u32(dsm);

    float acc[2][8][4];
#pragma unroll
    for (int a = 0; a < 2; a++)
#pragma unroll
        for (int b = 0; b < 8; b++)
#pragma unroll
            for (int q = 0; q < 4; q++) acc[a][b][q] = 0.f;

    // ---- stage loader: Ahi/Alo 128x32, Bhi/Blo 128x32 fp16, swizzled ----
    auto load_stage = [&](int kc, int s) {
        uint32_t st = sbase + s * STAGE_BYTES;
#pragma unroll
        for (int i = 0; i < 2; i++) {
            int cid = tid + i * 256;            // 0..511
            int row = cid >> 2, c = cid & 3;
            uint32_t off = row * 64 + ((c ^ ((row >> 1) & 3)) << 4);
            size_t ga = (size_t)(m0 + row) * 512 + kc * 32 + c * 8;
            size_t gb = (size_t)(n0 + row) * 512 + kc * 32 + c * 8;
            cpa16(st + off,                  Ahi + ga);
            cpa16(st + TILE_BYTES + off,     Alo + ga);
            cpa16(st + 2 * TILE_BYTES + off, Bhi + gb);
            cpa16(st + 3 * TILE_BYTES + off, Blo + gb);
        }
        cpa_commit();
    };

    // ---- per-chunk compute: stream B fragments one n-group (n16) at a time ----
    auto compute = [&](int s) {
        uint32_t st = sbase + s * STAGE_BYTES;
#pragma unroll
        for (int k16 = 0; k16 < 2; k16++) {
            uint32_t ahi[2][4], alo[2][4];
#pragma unroll
            for (int mt = 0; mt < 2; mt++) {
                int row = wm + mt * 16 + (lane & 7) + ((lane >> 3) & 1) * 8;
                int ch  = k16 * 2 + (lane >> 4);
                uint32_t off = row * 64 + ((ch ^ ((row >> 1) & 3)) << 4);
                ldsm4(ahi[mt], st + off);
                ldsm4(alo[mt], st + TILE_BYTES + off);
            }
#pragma unroll
            for (int ng = 0; ng < 4; ng++) {
                uint32_t bh[4], bl[4];
                int row = wn + ng * 16 + (lane & 7) + ((lane >> 4) & 1) * 8;
                int ch  = k16 * 2 + ((lane >> 3) & 1);
                uint32_t off = row * 64 + ((ch ^ ((row >> 1) & 3)) << 4);
                ldsm4(bh, st + 2 * TILE_BYTES + off);
                ldsm4(bl, st + 3 * TILE_BYTES + off);
#pragma unroll
                for (int mt = 0; mt < 2; mt++)
#pragma unroll
                    for (int nf = 0; nf < 2; nf++)
                        mma16816(acc[mt][ng * 2 + nf], ahi[mt], &bh[nf * 2]);
#pragma unroll
                for (int mt = 0; mt < 2; mt++)
#pragma unroll
                    for (int nf = 0; nf < 2; nf++)
                        mma16816(acc[mt][ng * 2 + nf], ahi[mt], &bl[nf * 2]);
#pragma unroll
                for (int mt = 0; mt < 2; mt++)
#pragma unroll
                    for (int nf = 0; nf < 2; nf++)
                        mma16816(acc[mt][ng * 2 + nf], alo[mt], &bh[nf * 2]);
            }
        }
    };

    // ---- 3-stage pipeline over 16 K-chunks ----
    load_stage(0, 0);
    load_stage(1, 1);
    for (int kc = 0; kc < 16; kc++) {
        cpa_wait<1>();
        __syncthreads();
        if (kc + 2 < 16) load_stage(kc + 2, (kc + 2) % NSTAGE);
        compute(kc % NSTAGE);
    }
    __syncthreads();   // all reads of stage smem done -> reuse as C tile

    // ---- spill accumulators to smem C tile [128][CSTRIDE] ----
    float* Cs = (float*)dsm;
#pragma unroll
    for (int mt = 0; mt < 2; mt++)
#pragma unroll
        for (int nf = 0; nf < 8; nf++) {
            int row = wm + mt * 16 + (lane >> 2);
            int col = wn + nf * 8 + (lane & 3) * 2;
            Cs[row * CSTRIDE + col]           = acc[mt][nf][0];
            Cs[row * CSTRIDE + col + 1]       = acc[mt][nf][1];
            Cs[(row + 8) * CSTRIDE + col]     = acc[mt][nf][2];
            Cs[(row + 8) * CSTRIDE + col + 1] = acc[mt][nf][3];
        }
    __syncthreads();

    // ---- final epilogue: thread -> (row ml, 64-col half) ----
    const int ml = tid >> 1;
    const int colbase = (tid & 1) * 64;
    const int m = m0 + ml;

    if (MODE == 0) {
#pragma unroll
        for (int q = 0; q < 16; q++) {
            int ncol = colbase + q * 4;
            float4 v  = *(float4*)&Cs[ml * CSTRIDE + ncol];
            float4 bv = *(const float4*)&bias[n0 + ncol];
            v.x += bv.x; v.y += bv.y; v.z += bv.z; v.w += bv.w;
            *(float4*)&Cout[(size_t)m * Ntot + n0 + ncol] = v;
        }
    } else {
        const int j0 = (n0 + colbase) >> 2;   // first hidden unit for this thread
        const int step0 = (sidx == 0);
        float cold[16];
#pragma unroll
        for (int q = 0; q < 16; q += 4) {
            float4 cv = *(const float4*)&c_in[(size_t)m * HD + j0 + q];
            cold[q] = cv.x; cold[q + 1] = cv.y; cold[q + 2] = cv.z; cold[q + 3] = cv.w;
        }
        float hbuf[16], cbuf[16];
#pragma unroll
        for (int q = 0; q < 16; q++) {
            int ncol = colbase + q * 4;
            float4 a  = *(float4*)&Cs[ml * CSTRIDE + ncol];
            float4 xv = *(const float4*)&xb[(size_t)m * G4 + n0 + ncol];
            float gi = a.x + xv.x, gf = a.y + xv.y, gg = a.z + xv.z, go = a.w + xv.w;
            if (step0) {
                float4 wf = *(const float4*)&wflag[n0 + ncol];
                gi += wf.x; gf += wf.y; gg += wf.z; go += wf.w;
            }
            float cn = sigf(gf) * cold[q] + sigf(gi) * tanh_acc(gg);
            float hn = sigf(go) * tanh_acc(cn);
            hbuf[q] = hn; cbuf[q] = cn;
        }
#pragma unroll
        for (int q = 0; q < 16; q += 4) {
            *(float4*)&h_out[(size_t)m * HD + j0 + q] = make_float4(hbuf[q], hbuf[q+1], hbuf[q+2], hbuf[q+3]);
            *(float4*)&c_out[(size_t)m * HD + j0 + q] = make_float4(cbuf[q], cbuf[q+1], cbuf[q+2], cbuf[q+3]);
        }
        __half hh[16], hl[16];
#pragma unroll
        for (int q = 0; q < 16; q++) {
            hh[q] = __float2half(hbuf[q]);
            hl[q] = __float2half(hbuf[q] - __half2float(hh[q]));
        }
        *(uint4*)&hhi_out[(size_t)m * HD + j0]     = *(uint4*)&hh[0];
        *(uint4*)&hhi_out[(size_t)m * HD + j0 + 8] = *(uint4*)&hh[8];
        *(uint4*)&hlo_out[(size_t)m * HD + j0]     = *(uint4*)&hl[0];
        *(uint4*)&hlo_out[(size_t)m * HD + j0 + 8] = *(uint4*)&hl[8];
    }
}

// ======================= per-step halt update (deterministic GEMV) =======================
// One warp per row: halt = sigmoid(h_s . W_halt + b); cum += halt; when ALL rows
// halted, last-arriving block sets g_max_needed = s (steps beyond are dead).
__global__ void halt_update(int s, const float* __restrict__ Whalt,
                            const float* __restrict__ bhalt)
{
    if (s > g_max_needed) return;
    __shared__ int s_cnt;
    if (threadIdx.x == 0) s_cnt = 0;
    __syncthreads();

    int warp = (blockIdx.x * blockDim.x + threadIdx.x) >> 5;
    int lane = threadIdx.x & 31;
    int halted = 0;
    if (warp < BD) {
        int m = warp;
        const float4* h4 = (const float4*)(g_hs + ((size_t)s * BD + m) * HD);
        const float4* w4 = (const float4*)Whalt;
        float sdot = 0.f;
#pragma unroll
        for (int it = 0; it < 4; it++) {
            float4 a = h4[lane + it * 32];
            float4 w = w4[lane + it * 32];
            sdot += a.x * w.x + a.y * w.y + a.z * w.z + a.w * w.w;
        }
#pragma unroll
        for (int off = 16; off; off >>= 1) sdot += __shfl_xor_sync(0xffffffffu, sdot, off);
        if (lane == 0) {
            float halt = sigf(sdot + bhalt[0]);
            float cum = g_cum[m] + halt;
            g_cum[m] = cum;
            g_halt[s * BD + m] = halt;
            if (cum >= 1.0f - 0.01f) halted = 1;
        }
    }
    if (halted) atomicAdd(&s_cnt, 1);
    __syncthreads();
    if (threadIdx.x == 0) {
        if (s_cnt) atomicAdd(&g_cnt[s], s_cnt);
        __threadfence();
        int arrived = atomicAdd(&g_arrive[s], 1);
        if (arrived == (int)gridDim.x - 1) {
            if (g_cnt[s] == BD) atomicMin(&g_max_needed, s);
        }
    }
}

// ======= pfin: halting scan + weighted reduce + fp16 split (halt_final merged) =======
__global__ void pfin(float* __restrict__ hfin, float* __restrict__ cfin,
                     float* __restrict__ ponder_out)
{
    int m = blockIdx.x;
    int j = threadIdx.x;   // 512 threads
    __shared__ float ps[NS];
    if (j == 0) {
        const float thresh = 1.0f - 0.01f;
        float halts[NS];
        float cum = 0.f; int nh = NS - 1; bool found = false;
#pragma unroll
        for (int n = 0; n < NS; n++) {
            halts[n] = g_halt[n * BD + m];   // stale beyond g_max_needed: p=0 there
            cum += halts[n];
            if (!found && cum >= thresh) { nh = n; found = true; }
        }
        float s = 0.f;
#pragma unroll
        for (int n = 0; n < NS; n++) {
            float p = (n < nh) ? halts[n] : 0.f;
            if (n < nh) s += p;
            ps[n] = p;
        }
        float r = 1.f - s;
        ps[nh] = r;
        ponder_out[m] = (float)nh + 1.f + r;
    }
    __syncthreads();
    float ah = 0.f, ac = 0.f;
#pragma unroll
    for (int n = 0; n < NS; n++) {
        float p = ps[n];
        if (p != 0.f) {                 // skip dead steps: no loads, identical sum
            size_t o = ((size_t)n * BD + m) * HD + j;
            ah += p * g_hs[o];
            ac += p * g_cs[o];
        }
    }
    hfin[(size_t)m * HD + j] = ah;
    cfin[(size_t)m * HD + j] = ac;
    __half hh = __float2half(ah);
    g_hf_hi[(size_t)m * HD + j] = hh;
    g_hf_lo[(size_t)m * HD + j] = __float2half(ah - __half2float(hh));
}

// ======================= launcher =======================
extern "C" void kernel_launch(void* const* d_in, const int* in_sizes, int n_in,
                              void* d_out, int out_size)
{
    const float* x     = (const float*)d_in[0];
    const float* h0    = (const float*)d_in[1];
    const float* c0    = (const float*)d_in[2];
    const float* Wih   = (const float*)d_in[3];
    const float* bih   = (const float*)d_in[4];
    const float* Whh   = (const float*)d_in[5];
    const float* bhh   = (const float*)d_in[6];
    const float* Whalt = (const float*)d_in[7];
    const float* bhalt = (const float*)d_in[8];
    const float* Wout  = (const float*)d_in[9];
    const float* bout  = (const float*)d_in[10];
    (void)in_sizes; (void)n_in; (void)out_size;

    float* out   = (float*)d_out;
    float* out_y = out;
    float* out_h = out + (size_t)BD * HD;
    float* out_c = out + (size_t)BD * HD * 2;
    float* out_p = out + (size_t)BD * HD * 3;

    cudaFuncSetAttribute(mma_gemm<0>, cudaFuncAttributeMaxDynamicSharedMemorySize, DSMEM_BYTES);
    cudaFuncSetAttribute(mma_gemm<1>, cudaFuncAttributeMaxDynamicSharedMemorySize, DSMEM_BYTES);

    __half *Whh_hi, *Whh_lo, *Wih_hi, *Wih_lo, *Wout_hi, *Wout_lo;
    __half *x_hi, *x_lo, *h_hi, *h_lo, *hf_hi, *hf_lo;
    float *wflag, *biasp, *xb, *hs, *cs;
    cudaGetSymbolAddress((void**)&Whh_hi, g_Whh_hi);
    cudaGetSymbolAddress((void**)&Whh_lo, g_Whh_lo);
    cudaGetSymbolAddress((void**)&Wih_hi, g_Wih_hi);
    cudaGetSymbolAddress((void**)&Wih_lo, g_Wih_lo);
    cudaGetSymbolAddress((void**)&Wout_hi, g_Wout_hi);
    cudaGetSymbolAddress((void**)&Wout_lo, g_Wout_lo);
    cudaGetSymbolAddress((void**)&x_hi, g_x_hi);
    cudaGetSymbolAddress((void**)&x_lo, g_x_lo);
    cudaGetSymbolAddress((void**)&h_hi, g_h_hi);
    cudaGetSymbolAddress((void**)&h_lo, g_h_lo);
    cudaGetSymbolAddress((void**)&hf_hi, g_hf_hi);
    cudaGetSymbolAddress((void**)&hf_lo, g_hf_lo);
    cudaGetSymbolAddress((void**)&wflag, g_wflag);
    cudaGetSymbolAddress((void**)&biasp, g_bias);
    cudaGetSymbolAddress((void**)&xb, g_xb);
    cudaGetSymbolAddress((void**)&hs, g_hs);
    cudaGetSymbolAddress((void**)&cs, g_cs);

    const size_t HBUF = (size_t)BD * HD;

    // 1) prep (also resets ACT state per launch)
    prep_weights<<<(G4 * HD + 255) / 256, 256>>>(Wih, Whh, bih, bhh);
    prep_data<<<(BD * HD + 255) / 256, 256>>>(x, h0, Wout);

    // 2) x-part: xb = x @ Wih_p^T + (b_ih + b_hh)
    dim3 gridG(G4 / 128, BD / 128);
    mma_gemm<0><<<gridG, 256, DSMEM_BYTES>>>(x_hi, x_lo, Wih_hi, Wih_lo, G4, biasp, xb,
                                             nullptr, nullptr, -1, nullptr, nullptr, nullptr,
                                             nullptr, nullptr);

    // 3) recurrent steps; each followed by halt bookkeeping. Steps beyond the
    //    all-halted point self-skip (p[n]=0 there -> outputs unaffected).
    for (int n = 0; n < NS; n++) {
        const float* c_i = (n == 0) ? c0 : (cs + (size_t)(n - 1) * HBUF);
        mma_gemm<1><<<gridG, 256, DSMEM_BYTES>>>(
            h_hi + (size_t)(n & 1) * HBUF, h_lo + (size_t)(n & 1) * HBUF,
            Whh_hi, Whh_lo, G4, nullptr, nullptr,
            xb, wflag, n,
            c_i, hs + (size_t)n * HBUF, cs + (size_t)n * HBUF,
            h_hi + (size_t)((n + 1) & 1) * HBUF, h_lo + (size_t)((n + 1) & 1) * HBUF);
        halt_update<<<BD / 8, 256>>>(n, Whalt, bhalt);
    }

    // 4) halting scan + h_fin / c_fin (+ fp16 split), skipping p==0 steps
    pfin<<<BD, HD>>>(out_h, out_c, out_p);

    // 5) output = h_fin @ W_out^T + b_out
    dim3 gridO(HD / 128, BD / 128);
    mma_gemm<0><<<gridO, 256, DSMEM_BYTES>>>(hf_hi, hf_lo, Wout_hi, Wout_lo, HD, bout, out_y,
                                             nullptr, nullptr, -1, nullptr, nullptr, nullptr,
                                             nullptr, nullptr);
}